// round 1
// baseline (speedup 1.0000x reference)
#include <cuda_runtime.h>
#include <math.h>

#define TOK 4096
#define DM 1024
#define DFF 4096

// ---------------- scratch (static device globals; no allocs) ----------------
__device__ float g_xn[TOK * DM];           // LN output (reused for LN1 and LN2)
__device__ float g_q[TOK * DM];
__device__ float g_k[TOK * DM];
__device__ float g_v[TOK * DM];
__device__ float g_att[TOK * DM];
__device__ float g_h1[TOK * DM];           // H after attention residual
__device__ float g_mlp[(size_t)TOK * DFF]; // GELU hidden

// ---------------- LayerNorm: one block per row ----------------
__global__ __launch_bounds__(256) void ln_kernel(const float* __restrict__ x,
                                                 const float* __restrict__ g,
                                                 const float* __restrict__ b,
                                                 float* __restrict__ out) {
    int row = blockIdx.x;
    int t = threadIdx.x;
    const float4* xr = (const float4*)(x + (size_t)row * DM);
    float4 v = xr[t];
    float s  = v.x + v.y + v.z + v.w;
    float ss = v.x * v.x + v.y * v.y + v.z * v.z + v.w * v.w;
    #pragma unroll
    for (int o = 16; o > 0; o >>= 1) {
        s  += __shfl_xor_sync(0xffffffffu, s, o);
        ss += __shfl_xor_sync(0xffffffffu, ss, o);
    }
    __shared__ float red[2][8];
    if ((t & 31) == 0) { red[0][t >> 5] = s; red[1][t >> 5] = ss; }
    __syncthreads();
    float ts = 0.f, tss = 0.f;
    #pragma unroll
    for (int i = 0; i < 8; i++) { ts += red[0][i]; tss += red[1][i]; }
    float mu   = ts * (1.0f / DM);
    float var  = tss * (1.0f / DM) - mu * mu;
    float rstd = rsqrtf(var + 1e-5f);
    float4 gv = ((const float4*)g)[t];
    float4 bv = ((const float4*)b)[t];
    float4 o;
    o.x = (v.x - mu) * rstd * gv.x + bv.x;
    o.y = (v.y - mu) * rstd * gv.y + bv.y;
    o.z = (v.z - mu) * rstd * gv.z + bv.z;
    o.w = (v.w - mu) * rstd * gv.w + bv.w;
    ((float4*)(out + (size_t)row * DM))[t] = o;
}

// ---------------- SGEMM: C[M,N] = A[M,K] @ B[K,N] (+ epilogue) ----------------
// EPI: 0 = none, 1 = +bias then exact GELU, 2 = +bias +res, 3 = +res
template <int EPI>
__global__ __launch_bounds__(256) void gemm_kernel(const float* __restrict__ A,
                                                   const float* __restrict__ B,
                                                   const float* __restrict__ bias,
                                                   const float* __restrict__ res,
                                                   float* __restrict__ C,
                                                   int M, int N, int K) {
    __shared__ float As[8][128];
    __shared__ float Bs[8][128];
    int t  = threadIdx.x;
    int bn = blockIdx.x, bm = blockIdx.y;
    int tx = t & 15, ty = t >> 4;

    int arow = t >> 1, aseg = (t & 1) << 2;       // A tile: 128 rows x 8 cols
    int brow = t >> 5, bcol = (t & 31) << 2;      // B tile: 8 rows x 128 cols
    const float* Ap = A + (size_t)(bm * 128 + arow) * K + aseg;
    const float* Bp = B + (size_t)brow * N + bn * 128 + bcol;

    float acc[8][8] = {};
    for (int k0 = 0; k0 < K; k0 += 8) {
        float4 av = *(const float4*)(Ap + k0);
        float4 bv = *(const float4*)(Bp + (size_t)k0 * N);
        As[aseg + 0][arow] = av.x;
        As[aseg + 1][arow] = av.y;
        As[aseg + 2][arow] = av.z;
        As[aseg + 3][arow] = av.w;
        *(float4*)&Bs[brow][bcol] = bv;
        __syncthreads();
        #pragma unroll
        for (int kk = 0; kk < 8; kk++) {
            float a[8], bb[8];
            *(float4*)(a)      = *(const float4*)&As[kk][ty * 8];
            *(float4*)(a + 4)  = *(const float4*)&As[kk][ty * 8 + 4];
            *(float4*)(bb)     = *(const float4*)&Bs[kk][tx * 8];
            *(float4*)(bb + 4) = *(const float4*)&Bs[kk][tx * 8 + 4];
            #pragma unroll
            for (int i = 0; i < 8; i++)
                #pragma unroll
                for (int j = 0; j < 8; j++)
                    acc[i][j] = fmaf(a[i], bb[j], acc[i][j]);
        }
        __syncthreads();
    }

    int row0 = bm * 128 + ty * 8;
    int col0 = bn * 128 + tx * 8;
    #pragma unroll
    for (int i = 0; i < 8; i++) {
        size_t ro = (size_t)(row0 + i) * N + col0;
        float v[8];
        #pragma unroll
        for (int j = 0; j < 8; j++) {
            float x = acc[i][j];
            if (EPI == 1) {
                x += bias[col0 + j];
                x = 0.5f * x * (1.0f + erff(x * 0.70710678118654752f));
            } else if (EPI == 2) {
                x += bias[col0 + j] + res[ro + j];
            } else if (EPI == 3) {
                x += res[ro + j];
            }
            v[j] = x;
        }
        *(float4*)(C + ro)     = make_float4(v[0], v[1], v[2], v[3]);
        *(float4*)(C + ro + 4) = make_float4(v[4], v[5], v[6], v[7]);
    }
}

// ---------------- Fused causal flash attention ----------------
// Q,K,V,O all [4096,1024] = [b*2048+t, h*64+d]. One block = (q-tile 64, head, batch).
// 256 threads as 16x16 micro-tiles of 4x4. Online softmax; P staged through K buffer.
#define ATTN_SMEM ((64 * 64 + 64 * 65 + 64 * 64) * 4)

__global__ __launch_bounds__(256) void attn_kernel(const float* __restrict__ Q,
                                                   const float* __restrict__ K,
                                                   const float* __restrict__ V,
                                                   float* __restrict__ O) {
    extern __shared__ float sm[];
    float* sQ  = sm;                 // 64 x 64
    float* sKP = sm + 64 * 64;       // 64 x 65  (K tile, then P tile)
    float* sV  = sKP + 64 * 65;      // 64 x 64

    int qb = blockIdx.x, h = blockIdx.y, bb = blockIdx.z;
    int t = threadIdx.x;
    int mrow = t >> 4, mcol = t & 15;
    int r0 = mrow << 2, c0 = mcol << 2;
    size_t base = ((size_t)bb * 2048) * DM + (size_t)h * 64;

    // load Q tile
    #pragma unroll
    for (int i = 0; i < 4; i++) {
        int idx = t + i * 256;
        int r = idx >> 4, c4 = (idx & 15) << 2;
        *(float4*)&sQ[r * 64 + c4] =
            *(const float4*)(Q + base + (size_t)(qb * 64 + r) * DM + c4);
    }

    float acc[4][4];
    float m[4], l[4];
    #pragma unroll
    for (int i = 0; i < 4; i++) {
        m[i] = -1e30f; l[i] = 0.f;
        #pragma unroll
        for (int j = 0; j < 4; j++) acc[i][j] = 0.f;
    }

    for (int kb = 0; kb <= qb; kb++) {
        __syncthreads();  // prior PV reads (and Q writes on first iter) complete
        // load K -> sKP (scalar stores, stride 65), V -> sV
        #pragma unroll
        for (int i = 0; i < 4; i++) {
            int idx = t + i * 256;
            int r = idx >> 4, c4 = (idx & 15) << 2;
            float4 kv = *(const float4*)(K + base + (size_t)(kb * 64 + r) * DM + c4);
            sKP[r * 65 + c4 + 0] = kv.x;
            sKP[r * 65 + c4 + 1] = kv.y;
            sKP[r * 65 + c4 + 2] = kv.z;
            sKP[r * 65 + c4 + 3] = kv.w;
            *(float4*)&sV[r * 64 + c4] =
                *(const float4*)(V + base + (size_t)(kb * 64 + r) * DM + c4);
        }
        __syncthreads();

        // S = (Q K^T) * 1/8
        float s[4][4] = {};
        #pragma unroll 8
        for (int d = 0; d < 64; d++) {
            float qv[4], kv[4];
            #pragma unroll
            for (int i = 0; i < 4; i++) qv[i] = sQ[(r0 + i) * 64 + d];
            #pragma unroll
            for (int j = 0; j < 4; j++) kv[j] = sKP[(c0 + j) * 65 + d];
            #pragma unroll
            for (int i = 0; i < 4; i++)
                #pragma unroll
                for (int j = 0; j < 4; j++)
                    s[i][j] = fmaf(qv[i], kv[j], s[i][j]);
        }
        #pragma unroll
        for (int i = 0; i < 4; i++)
            #pragma unroll
            for (int j = 0; j < 4; j++) s[i][j] *= 0.125f;
        if (kb == qb) {  // causal mask on diagonal tile
            #pragma unroll
            for (int i = 0; i < 4; i++)
                #pragma unroll
                for (int j = 0; j < 4; j++)
                    if (c0 + j > r0 + i) s[i][j] = -1e30f;
        }

        // online softmax update (row groups = 16 lanes within a half-warp)
        float mt[4], mn[4], corr[4], rs[4];
        #pragma unroll
        for (int i = 0; i < 4; i++) {
            mt[i] = fmaxf(fmaxf(s[i][0], s[i][1]), fmaxf(s[i][2], s[i][3]));
            #pragma unroll
            for (int o = 8; o > 0; o >>= 1)
                mt[i] = fmaxf(mt[i], __shfl_xor_sync(0xffffffffu, mt[i], o));
            mn[i]   = fmaxf(m[i], mt[i]);
            corr[i] = __expf(m[i] - mn[i]);
            m[i]    = mn[i];
        }
        float p[4][4];
        #pragma unroll
        for (int i = 0; i < 4; i++) {
            rs[i] = 0.f;
            #pragma unroll
            for (int j = 0; j < 4; j++) {
                p[i][j] = __expf(s[i][j] - mn[i]);
                rs[i] += p[i][j];
            }
            #pragma unroll
            for (int o = 8; o > 0; o >>= 1)
                rs[i] += __shfl_xor_sync(0xffffffffu, rs[i], o);
            l[i] = l[i] * corr[i] + rs[i];
            #pragma unroll
            for (int j = 0; j < 4; j++) acc[i][j] *= corr[i];
        }

        __syncthreads();  // all S reads of K done before overwriting with P
        #pragma unroll
        for (int i = 0; i < 4; i++)
            #pragma unroll
            for (int j = 0; j < 4; j++)
                sKP[(r0 + i) * 65 + c0 + j] = p[i][j];
        __syncthreads();

        // acc += P @ V
        #pragma unroll 8
        for (int c = 0; c < 64; c++) {
            float pv[4];
            #pragma unroll
            for (int i = 0; i < 4; i++) pv[i] = sKP[(r0 + i) * 65 + c];
            float4 vv = *(const float4*)&sV[c * 64 + c0];
            #pragma unroll
            for (int i = 0; i < 4; i++) {
                acc[i][0] = fmaf(pv[i], vv.x, acc[i][0]);
                acc[i][1] = fmaf(pv[i], vv.y, acc[i][1]);
                acc[i][2] = fmaf(pv[i], vv.z, acc[i][2]);
                acc[i][3] = fmaf(pv[i], vv.w, acc[i][3]);
            }
        }
    }

    #pragma unroll
    for (int i = 0; i < 4; i++) {
        float inv = 1.0f / l[i];
        float4 o = make_float4(acc[i][0] * inv, acc[i][1] * inv,
                               acc[i][2] * inv, acc[i][3] * inv);
        *(float4*)(O + base + (size_t)(qb * 64 + r0 + i) * DM + c0) = o;
    }
}

// ---------------- launch ----------------
extern "C" void kernel_launch(void* const* d_in, const int* in_sizes, int n_in,
                              void* d_out, int out_size) {
    const float* H    = (const float*)d_in[0];
    const float* Wq   = (const float*)d_in[1];
    const float* Wk   = (const float*)d_in[2];
    const float* Wv   = (const float*)d_in[3];
    const float* Wo   = (const float*)d_in[4];
    const float* ln1g = (const float*)d_in[5];
    const float* ln1b = (const float*)d_in[6];
    const float* ln2g = (const float*)d_in[7];
    const float* ln2b = (const float*)d_in[8];
    const float* W1   = (const float*)d_in[9];
    const float* b1   = (const float*)d_in[10];
    const float* W2   = (const float*)d_in[11];
    const float* b2   = (const float*)d_in[12];
    float* out = (float*)d_out;

    float *xn, *q, *k, *v, *att, *h1, *mlp;
    cudaGetSymbolAddress((void**)&xn,  g_xn);
    cudaGetSymbolAddress((void**)&q,   g_q);
    cudaGetSymbolAddress((void**)&k,   g_k);
    cudaGetSymbolAddress((void**)&v,   g_v);
    cudaGetSymbolAddress((void**)&att, g_att);
    cudaGetSymbolAddress((void**)&h1,  g_h1);
    cudaGetSymbolAddress((void**)&mlp, g_mlp);

    cudaFuncSetAttribute(attn_kernel, cudaFuncAttributeMaxDynamicSharedMemorySize,
                         ATTN_SMEM);

    dim3 gProj(DM / 128, TOK / 128);   // 8 x 32
    dim3 gMlp1(DFF / 128, TOK / 128);  // 32 x 32

    // LN1
    ln_kernel<<<TOK, 256>>>(H, ln1g, ln1b, xn);
    // Q, K, V projections
    gemm_kernel<0><<<gProj, 256>>>(xn, Wq, nullptr, nullptr, q, TOK, DM, DM);
    gemm_kernel<0><<<gProj, 256>>>(xn, Wk, nullptr, nullptr, k, TOK, DM, DM);
    gemm_kernel<0><<<gProj, 256>>>(xn, Wv, nullptr, nullptr, v, TOK, DM, DM);
    // fused causal attention
    attn_kernel<<<dim3(32, 16, 2), 256, ATTN_SMEM>>>(q, k, v, att);
    // O projection + residual
    gemm_kernel<3><<<gProj, 256>>>(att, Wo, nullptr, H, h1, TOK, DM, DM);
    // LN2
    ln_kernel<<<TOK, 256>>>(h1, ln2g, ln2b, xn);
    // MLP
    gemm_kernel<1><<<gMlp1, 256>>>(xn, W1, b1, nullptr, mlp, TOK, DFF, DM);
    gemm_kernel<2><<<gProj, 256>>>(mlp, W2, b2, h1, out, TOK, DM, DFF);
}

// round 2
// speedup vs baseline: 1.0044x; 1.0044x over previous
#include <cuda_runtime.h>
#include <math.h>

#define TOK 4096
#define DM 1024
#define DFF 4096

// ---------------- scratch (static device globals; no allocs) ----------------
__device__ float g_xn[TOK * DM];           // LN output (reused for LN1 and LN2)
__device__ float g_q[TOK * DM];
__device__ float g_k[TOK * DM];
__device__ float g_v[TOK * DM];
__device__ float g_att[TOK * DM];
__device__ float g_h1[TOK * DM];           // H after attention residual
__device__ float g_mlp[(size_t)TOK * DFF]; // GELU hidden

// ---------------- LayerNorm: one block per row ----------------
__global__ __launch_bounds__(256) void ln_kernel(const float* __restrict__ x,
                                                 const float* __restrict__ g,
                                                 const float* __restrict__ b,
                                                 float* __restrict__ out) {
    int row = blockIdx.x;
    int t = threadIdx.x;
    const float4* xr = (const float4*)(x + (size_t)row * DM);
    float4 v = xr[t];
    float s  = v.x + v.y + v.z + v.w;
    float ss = v.x * v.x + v.y * v.y + v.z * v.z + v.w * v.w;
    #pragma unroll
    for (int o = 16; o > 0; o >>= 1) {
        s  += __shfl_xor_sync(0xffffffffu, s, o);
        ss += __shfl_xor_sync(0xffffffffu, ss, o);
    }
    __shared__ float red[2][8];
    if ((t & 31) == 0) { red[0][t >> 5] = s; red[1][t >> 5] = ss; }
    __syncthreads();
    float ts = 0.f, tss = 0.f;
    #pragma unroll
    for (int i = 0; i < 8; i++) { ts += red[0][i]; tss += red[1][i]; }
    float mu   = ts * (1.0f / DM);
    float var  = tss * (1.0f / DM) - mu * mu;
    float rstd = rsqrtf(var + 1e-5f);
    float4 gv = ((const float4*)g)[t];
    float4 bv = ((const float4*)b)[t];
    float4 o;
    o.x = (v.x - mu) * rstd * gv.x + bv.x;
    o.y = (v.y - mu) * rstd * gv.y + bv.y;
    o.z = (v.z - mu) * rstd * gv.z + bv.z;
    o.w = (v.w - mu) * rstd * gv.w + bv.w;
    ((float4*)(out + (size_t)row * DM))[t] = o;
}

// ---------------- SGEMM: C[M,N] = A[M,K] @ B[K,N] (+ epilogue) ----------------
// EPI: 0 = none, 1 = +bias then exact GELU, 2 = +bias +res, 3 = +res
template <int EPI>
__global__ __launch_bounds__(256) void gemm_kernel(const float* __restrict__ A,
                                                   const float* __restrict__ B,
                                                   const float* __restrict__ bias,
                                                   const float* __restrict__ res,
                                                   float* __restrict__ C,
                                                   int M, int N, int K) {
    __shared__ float As[8][128];
    __shared__ float Bs[8][128];
    int t  = threadIdx.x;
    int bn = blockIdx.x, bm = blockIdx.y;
    int tx = t & 15, ty = t >> 4;

    int arow = t >> 1, aseg = (t & 1) << 2;       // A tile: 128 rows x 8 cols
    int brow = t >> 5, bcol = (t & 31) << 2;      // B tile: 8 rows x 128 cols
    const float* Ap = A + (size_t)(bm * 128 + arow) * K + aseg;
    const float* Bp = B + (size_t)brow * N + bn * 128 + bcol;

    float acc[8][8] = {};
    for (int k0 = 0; k0 < K; k0 += 8) {
        float4 av = *(const float4*)(Ap + k0);
        float4 bv = *(const float4*)(Bp + (size_t)k0 * N);
        As[aseg + 0][arow] = av.x;
        As[aseg + 1][arow] = av.y;
        As[aseg + 2][arow] = av.z;
        As[aseg + 3][arow] = av.w;
        *(float4*)&Bs[brow][bcol] = bv;
        __syncthreads();
        #pragma unroll
        for (int kk = 0; kk < 8; kk++) {
            float a[8], bb[8];
            *(float4*)(a)      = *(const float4*)&As[kk][ty * 8];
            *(float4*)(a + 4)  = *(const float4*)&As[kk][ty * 8 + 4];
            *(float4*)(bb)     = *(const float4*)&Bs[kk][tx * 8];
            *(float4*)(bb + 4) = *(const float4*)&Bs[kk][tx * 8 + 4];
            #pragma unroll
            for (int i = 0; i < 8; i++)
                #pragma unroll
                for (int j = 0; j < 8; j++)
                    acc[i][j] = fmaf(a[i], bb[j], acc[i][j]);
        }
        __syncthreads();
    }

    int row0 = bm * 128 + ty * 8;
    int col0 = bn * 128 + tx * 8;
    #pragma unroll
    for (int i = 0; i < 8; i++) {
        size_t ro = (size_t)(row0 + i) * N + col0;
        float v[8];
        #pragma unroll
        for (int j = 0; j < 8; j++) {
            float x = acc[i][j];
            if (EPI == 1) {
                x += bias[col0 + j];
                x = 0.5f * x * (1.0f + erff(x * 0.70710678118654752f));
            } else if (EPI == 2) {
                x += bias[col0 + j] + res[ro + j];
            } else if (EPI == 3) {
                x += res[ro + j];
            }
            v[j] = x;
        }
        *(float4*)(C + ro)     = make_float4(v[0], v[1], v[2], v[3]);
        *(float4*)(C + ro + 4) = make_float4(v[4], v[5], v[6], v[7]);
    }
}

// ---------------- Fused causal flash attention ----------------
// Q,K,V,O all [4096,1024] = [b*2048+t, h*64+d]. One block = (q-tile 64, head, batch).
// 256 threads as 16x16 micro-tiles of 4x4. Online softmax; P staged through K buffer.
#define ATTN_SMEM ((64 * 64 + 64 * 65 + 64 * 64) * 4)

__global__ __launch_bounds__(256) void attn_kernel(const float* __restrict__ Q,
                                                   const float* __restrict__ K,
                                                   const float* __restrict__ V,
                                                   float* __restrict__ O) {
    extern __shared__ float sm[];
    float* sQ  = sm;                 // 64 x 64
    float* sKP = sm + 64 * 64;       // 64 x 65  (K tile, then P tile)
    float* sV  = sKP + 64 * 65;      // 64 x 64

    int qb = blockIdx.x, h = blockIdx.y, bb = blockIdx.z;
    int t = threadIdx.x;
    int mrow = t >> 4, mcol = t & 15;
    int r0 = mrow << 2, c0 = mcol << 2;
    size_t base = ((size_t)bb * 2048) * DM + (size_t)h * 64;

    // load Q tile
    #pragma unroll
    for (int i = 0; i < 4; i++) {
        int idx = t + i * 256;
        int r = idx >> 4, c4 = (idx & 15) << 2;
        *(float4*)&sQ[r * 64 + c4] =
            *(const float4*)(Q + base + (size_t)(qb * 64 + r) * DM + c4);
    }

    float acc[4][4];
    float m[4], l[4];
    #pragma unroll
    for (int i = 0; i < 4; i++) {
        m[i] = -1e30f; l[i] = 0.f;
        #pragma unroll
        for (int j = 0; j < 4; j++) acc[i][j] = 0.f;
    }

    for (int kb = 0; kb <= qb; kb++) {
        __syncthreads();  // prior PV reads (and Q writes on first iter) complete
        // load K -> sKP (scalar stores, stride 65), V -> sV
        #pragma unroll
        for (int i = 0; i < 4; i++) {
            int idx = t + i * 256;
            int r = idx >> 4, c4 = (idx & 15) << 2;
            float4 kv = *(const float4*)(K + base + (size_t)(kb * 64 + r) * DM + c4);
            sKP[r * 65 + c4 + 0] = kv.x;
            sKP[r * 65 + c4 + 1] = kv.y;
            sKP[r * 65 + c4 + 2] = kv.z;
            sKP[r * 65 + c4 + 3] = kv.w;
            *(float4*)&sV[r * 64 + c4] =
                *(const float4*)(V + base + (size_t)(kb * 64 + r) * DM + c4);
        }
        __syncthreads();

        // S = (Q K^T) * 1/8
        float s[4][4] = {};
        #pragma unroll 8
        for (int d = 0; d < 64; d++) {
            float qv[4], kv[4];
            #pragma unroll
            for (int i = 0; i < 4; i++) qv[i] = sQ[(r0 + i) * 64 + d];
            #pragma unroll
            for (int j = 0; j < 4; j++) kv[j] = sKP[(c0 + j) * 65 + d];
            #pragma unroll
            for (int i = 0; i < 4; i++)
                #pragma unroll
                for (int j = 0; j < 4; j++)
                    s[i][j] = fmaf(qv[i], kv[j], s[i][j]);
        }
        #pragma unroll
        for (int i = 0; i < 4; i++)
            #pragma unroll
            for (int j = 0; j < 4; j++) s[i][j] *= 0.125f;
        if (kb == qb) {  // causal mask on diagonal tile
            #pragma unroll
            for (int i = 0; i < 4; i++)
                #pragma unroll
                for (int j = 0; j < 4; j++)
                    if (c0 + j > r0 + i) s[i][j] = -1e30f;
        }

        // online softmax update (row groups = 16 lanes within a half-warp)
        float mt[4], mn[4], corr[4], rs[4];
        #pragma unroll
        for (int i = 0; i < 4; i++) {
            mt[i] = fmaxf(fmaxf(s[i][0], s[i][1]), fmaxf(s[i][2], s[i][3]));
            #pragma unroll
            for (int o = 8; o > 0; o >>= 1)
                mt[i] = fmaxf(mt[i], __shfl_xor_sync(0xffffffffu, mt[i], o));
            mn[i]   = fmaxf(m[i], mt[i]);
            corr[i] = __expf(m[i] - mn[i]);
            m[i]    = mn[i];
        }
        float p[4][4];
        #pragma unroll
        for (int i = 0; i < 4; i++) {
            rs[i] = 0.f;
            #pragma unroll
            for (int j = 0; j < 4; j++) {
                p[i][j] = __expf(s[i][j] - mn[i]);
                rs[i] += p[i][j];
            }
            #pragma unroll
            for (int o = 8; o > 0; o >>= 1)
                rs[i] += __shfl_xor_sync(0xffffffffu, rs[i], o);
            l[i] = l[i] * corr[i] + rs[i];
            #pragma unroll
            for (int j = 0; j < 4; j++) acc[i][j] *= corr[i];
        }

        __syncthreads();  // all S reads of K done before overwriting with P
        #pragma unroll
        for (int i = 0; i < 4; i++)
            #pragma unroll
            for (int j = 0; j < 4; j++)
                sKP[(r0 + i) * 65 + c0 + j] = p[i][j];
        __syncthreads();

        // acc += P @ V
        #pragma unroll 8
        for (int c = 0; c < 64; c++) {
            float pv[4];
            #pragma unroll
            for (int i = 0; i < 4; i++) pv[i] = sKP[(r0 + i) * 65 + c];
            float4 vv = *(const float4*)&sV[c * 64 + c0];
            #pragma unroll
            for (int i = 0; i < 4; i++) {
                acc[i][0] = fmaf(pv[i], vv.x, acc[i][0]);
                acc[i][1] = fmaf(pv[i], vv.y, acc[i][1]);
                acc[i][2] = fmaf(pv[i], vv.z, acc[i][2]);
                acc[i][3] = fmaf(pv[i], vv.w, acc[i][3]);
            }
        }
    }

    #pragma unroll
    for (int i = 0; i < 4; i++) {
        float inv = 1.0f / l[i];
        float4 o = make_float4(acc[i][0] * inv, acc[i][1] * inv,
                               acc[i][2] * inv, acc[i][3] * inv);
        *(float4*)(O + base + (size_t)(qb * 64 + r0 + i) * DM + c0) = o;
    }
}

// ---------------- launch ----------------
extern "C" void kernel_launch(void* const* d_in, const int* in_sizes, int n_in,
                              void* d_out, int out_size) {
    const float* H    = (const float*)d_in[0];
    const float* Wq   = (const float*)d_in[1];
    const float* Wk   = (const float*)d_in[2];
    const float* Wv   = (const float*)d_in[3];
    const float* Wo   = (const float*)d_in[4];
    const float* ln1g = (const float*)d_in[5];
    const float* ln1b = (const float*)d_in[6];
    const float* ln2g = (const float*)d_in[7];
    const float* ln2b = (const float*)d_in[8];
    const float* W1   = (const float*)d_in[9];
    const float* b1   = (const float*)d_in[10];
    const float* W2   = (const float*)d_in[11];
    const float* b2   = (const float*)d_in[12];
    float* out = (float*)d_out;

    float *xn, *q, *k, *v, *att, *h1, *mlp;
    cudaGetSymbolAddress((void**)&xn,  g_xn);
    cudaGetSymbolAddress((void**)&q,   g_q);
    cudaGetSymbolAddress((void**)&k,   g_k);
    cudaGetSymbolAddress((void**)&v,   g_v);
    cudaGetSymbolAddress((void**)&att, g_att);
    cudaGetSymbolAddress((void**)&h1,  g_h1);
    cudaGetSymbolAddress((void**)&mlp, g_mlp);

    cudaFuncSetAttribute(attn_kernel, cudaFuncAttributeMaxDynamicSharedMemorySize,
                         ATTN_SMEM);

    dim3 gProj(DM / 128, TOK / 128);   // 8 x 32
    dim3 gMlp1(DFF / 128, TOK / 128);  // 32 x 32

    // LN1
    ln_kernel<<<TOK, 256>>>(H, ln1g, ln1b, xn);
    // Q, K, V projections
    gemm_kernel<0><<<gProj, 256>>>(xn, Wq, nullptr, nullptr, q, TOK, DM, DM);
    gemm_kernel<0><<<gProj, 256>>>(xn, Wk, nullptr, nullptr, k, TOK, DM, DM);
    gemm_kernel<0><<<gProj, 256>>>(xn, Wv, nullptr, nullptr, v, TOK, DM, DM);
    // fused causal attention
    attn_kernel<<<dim3(32, 16, 2), 256, ATTN_SMEM>>>(q, k, v, att);
    // O projection + residual
    gemm_kernel<3><<<gProj, 256>>>(att, Wo, nullptr, H, h1, TOK, DM, DM);
    // LN2
    ln_kernel<<<TOK, 256>>>(h1, ln2g, ln2b, xn);
    // MLP
    gemm_kernel<1><<<gMlp1, 256>>>(xn, W1, b1, nullptr, mlp, TOK, DFF, DM);
    gemm_kernel<2><<<gProj, 256>>>(mlp, W2, b2, h1, out, TOK, DM, DFF);
}

// round 4
// speedup vs baseline: 2.5505x; 2.5392x over previous
#include <cuda_runtime.h>
#include <stdint.h>
#include <math.h>

#define TOK 4096
#define DM 1024
#define DFF 4096

// ---------------- scratch (static device globals; no allocs) ----------------
__device__ float g_xn[TOK * DM];           // LN output (reused for LN1 and LN2)
__device__ float g_q[TOK * DM];
__device__ float g_k[TOK * DM];
__device__ float g_v[TOK * DM];
__device__ float g_att[TOK * DM];
__device__ float g_h1[TOK * DM];           // H after attention residual
__device__ float g_mlp[(size_t)TOK * DFF]; // GELU hidden

// ---------------- LayerNorm: one block per row ----------------
__global__ __launch_bounds__(256) void ln_kernel(const float* __restrict__ x,
                                                 const float* __restrict__ g,
                                                 const float* __restrict__ b,
                                                 float* __restrict__ out) {
    int row = blockIdx.x;
    int t = threadIdx.x;
    const float4* xr = (const float4*)(x + (size_t)row * DM);
    float4 v = xr[t];
    float s  = v.x + v.y + v.z + v.w;
    float ss = v.x * v.x + v.y * v.y + v.z * v.z + v.w * v.w;
    #pragma unroll
    for (int o = 16; o > 0; o >>= 1) {
        s  += __shfl_xor_sync(0xffffffffu, s, o);
        ss += __shfl_xor_sync(0xffffffffu, ss, o);
    }
    __shared__ float red[2][8];
    if ((t & 31) == 0) { red[0][t >> 5] = s; red[1][t >> 5] = ss; }
    __syncthreads();
    float ts = 0.f, tss = 0.f;
    #pragma unroll
    for (int i = 0; i < 8; i++) { ts += red[0][i]; tss += red[1][i]; }
    float mu   = ts * (1.0f / DM);
    float var  = tss * (1.0f / DM) - mu * mu;
    float rstd = rsqrtf(var + 1e-5f);
    float4 gv = ((const float4*)g)[t];
    float4 bv = ((const float4*)b)[t];
    float4 o;
    o.x = (v.x - mu) * rstd * gv.x + bv.x;
    o.y = (v.y - mu) * rstd * gv.y + bv.y;
    o.z = (v.z - mu) * rstd * gv.z + bv.z;
    o.w = (v.w - mu) * rstd * gv.w + bv.w;
    ((float4*)(out + (size_t)row * DM))[t] = o;
}

// ---------------- TF32 tensor-core GEMM ----------------
// C[M,N] = A[M,K] @ B[K,N] (+ epilogue)
// EPI: 0 = none, 1 = +bias then exact GELU, 2 = +bias +res, 3 = +res
// Block tile 128x128x32, 8 warps as 2(m) x 4(n); per warp 4x4 m16n8k8 tiles.
// Double-buffered smem via cp.async. Padded strides give conflict-free
// fragment loads (A stride 36, B stride 136).

#define ASTR 36
#define BSTR 136
#define ASZ (128 * ASTR)
#define BSZ (32 * BSTR)
#define GEMM_SMEM ((ASZ + BSZ) * 2 * sizeof(float))

__device__ __forceinline__ uint32_t f2tf32(float x) {
    uint32_t r;
    asm("cvt.rna.tf32.f32 %0, %1;" : "=r"(r) : "f"(x));
    return r;
}

__device__ __forceinline__ void mma_tf32(float c[4],
                                         uint32_t a0, uint32_t a1,
                                         uint32_t a2, uint32_t a3,
                                         uint32_t b0, uint32_t b1) {
    asm volatile(
        "mma.sync.aligned.m16n8k8.row.col.f32.tf32.tf32.f32 "
        "{%0,%1,%2,%3}, {%4,%5,%6,%7}, {%8,%9}, {%0,%1,%2,%3};\n"
        : "+f"(c[0]), "+f"(c[1]), "+f"(c[2]), "+f"(c[3])
        : "r"(a0), "r"(a1), "r"(a2), "r"(a3), "r"(b0), "r"(b1));
}

__device__ __forceinline__ void cp_async16(uint32_t smem, const void* gptr) {
    asm volatile("cp.async.cg.shared.global [%0], [%1], 16;\n"
                 :: "r"(smem), "l"(gptr));
}

template <int EPI>
__global__ __launch_bounds__(256) void gemm_tf32(const float* __restrict__ A,
                                                 const float* __restrict__ B,
                                                 const float* __restrict__ bias,
                                                 const float* __restrict__ res,
                                                 float* __restrict__ C,
                                                 int M, int N, int K) {
    extern __shared__ float sm[];
    uint32_t sbase = (uint32_t)__cvta_generic_to_shared(sm);

    int t = threadIdx.x;
    int bn = blockIdx.x, bm = blockIdx.y;
    int wid = t >> 5, lane = t & 31;
    int wm = wid & 1, wn = wid >> 1;          // 2 x 4 warp grid
    int g = lane >> 2, tig = lane & 3;

    const float* Abase = A + (size_t)(bm * 128) * K;
    const float* Bbase = B + bn * 128;

    // async tile loader: chunk k0 -> buffer buf
    auto load_tiles = [&](int k0, int buf) {
        uint32_t sa = sbase + (uint32_t)(buf * (ASZ + BSZ)) * 4u;
        uint32_t sb = sa + (uint32_t)ASZ * 4u;
        const float* Ap = Abase + k0;
        const float* Bp = Bbase + (size_t)k0 * N;
        #pragma unroll
        for (int i = 0; i < 4; i++) {          // A: 128 rows x 32 cols
            int idx = t + i * 256;
            int r = idx >> 3, c4 = (idx & 7) << 2;
            cp_async16(sa + (uint32_t)(r * ASTR + c4) * 4u,
                       Ap + (size_t)r * K + c4);
        }
        #pragma unroll
        for (int i = 0; i < 4; i++) {          // B: 32 rows x 128 cols
            int idx = t + i * 256;
            int r = idx >> 5, c4 = (idx & 31) << 2;
            cp_async16(sb + (uint32_t)(r * BSTR + c4) * 4u,
                       Bp + (size_t)r * N + c4);
        }
        asm volatile("cp.async.commit_group;\n");
    };

    float acc[4][4][4];
    #pragma unroll
    for (int i = 0; i < 4; i++)
        #pragma unroll
        for (int j = 0; j < 4; j++)
            #pragma unroll
            for (int r = 0; r < 4; r++) acc[i][j][r] = 0.f;

    load_tiles(0, 0);
    int NC = K >> 5;
    for (int c = 0; c < NC; c++) {
        asm volatile("cp.async.wait_group 0;\n");
        __syncthreads();
        if (c + 1 < NC) load_tiles((c + 1) << 5, (c + 1) & 1);

        const float* a = sm + (c & 1) * (ASZ + BSZ);
        const float* b = a + ASZ;

        #pragma unroll
        for (int ks = 0; ks < 4; ks++) {
            int kc = ks * 8;
            uint32_t af[4][4], bf[4][2];
            #pragma unroll
            for (int mt = 0; mt < 4; mt++) {
                int r = wm * 64 + mt * 16 + g;
                af[mt][0] = f2tf32(a[r * ASTR + kc + tig]);
                af[mt][1] = f2tf32(a[(r + 8) * ASTR + kc + tig]);
                af[mt][2] = f2tf32(a[r * ASTR + kc + tig + 4]);
                af[mt][3] = f2tf32(a[(r + 8) * ASTR + kc + tig + 4]);
            }
            #pragma unroll
            for (int nt = 0; nt < 4; nt++) {
                int cn = wn * 32 + nt * 8 + g;
                bf[nt][0] = f2tf32(b[(kc + tig) * BSTR + cn]);
                bf[nt][1] = f2tf32(b[(kc + tig + 4) * BSTR + cn]);
            }
            #pragma unroll
            for (int mt = 0; mt < 4; mt++)
                #pragma unroll
                for (int nt = 0; nt < 4; nt++)
                    mma_tf32(acc[mt][nt], af[mt][0], af[mt][1], af[mt][2],
                             af[mt][3], bf[nt][0], bf[nt][1]);
        }
        __syncthreads();
    }

    // epilogue: element (row, col): row = bm*128 + wm*64 + mt*16 + half*8 + g
    //                               col = bn*128 + wn*32 + nt*8 + tig*2 (+1)
    int row0 = bm * 128 + wm * 64;
    int col0 = bn * 128 + wn * 32;
    #pragma unroll
    for (int mt = 0; mt < 4; mt++) {
        #pragma unroll
        for (int half = 0; half < 2; half++) {
            int r = row0 + mt * 16 + half * 8 + g;
            size_t rb = (size_t)r * N;
            #pragma unroll
            for (int nt = 0; nt < 4; nt++) {
                int cn = col0 + nt * 8 + tig * 2;
                float x0 = acc[mt][nt][half * 2];
                float x1 = acc[mt][nt][half * 2 + 1];
                if (EPI == 1) {
                    x0 += bias[cn];
                    x1 += bias[cn + 1];
                    x0 = 0.5f * x0 * (1.0f + erff(x0 * 0.70710678118654752f));
                    x1 = 0.5f * x1 * (1.0f + erff(x1 * 0.70710678118654752f));
                } else if (EPI == 2) {
                    x0 += bias[cn] + res[rb + cn];
                    x1 += bias[cn + 1] + res[rb + cn + 1];
                } else if (EPI == 3) {
                    x0 += res[rb + cn];
                    x1 += res[rb + cn + 1];
                }
                *(float2*)(C + rb + cn) = make_float2(x0, x1);
            }
        }
    }
}

// ---------------- Fused causal flash attention ----------------
// Q,K,V,O all [4096,1024] = [b*2048+t, h*64+d]. One block = (q-tile 64, head, batch).
// 256 threads as 16x16 micro-tiles of 4x4. Online softmax; P staged through K buffer.
#define ATTN_SMEM ((64 * 64 + 64 * 65 + 64 * 64) * 4)

__global__ __launch_bounds__(256) void attn_kernel(const float* __restrict__ Q,
                                                   const float* __restrict__ K,
                                                   const float* __restrict__ V,
                                                   float* __restrict__ O) {
    extern __shared__ float sm[];
    float* sQ  = sm;                 // 64 x 64
    float* sKP = sm + 64 * 64;       // 64 x 65  (K tile, then P tile)
    float* sV  = sKP + 64 * 65;      // 64 x 64

    int qb = blockIdx.x, h = blockIdx.y, bb = blockIdx.z;
    int t = threadIdx.x;
    int mrow = t >> 4, mcol = t & 15;
    int r0 = mrow << 2, c0 = mcol << 2;
    size_t base = ((size_t)bb * 2048) * DM + (size_t)h * 64;

    // load Q tile
    #pragma unroll
    for (int i = 0; i < 4; i++) {
        int idx = t + i * 256;
        int r = idx >> 4, c4 = (idx & 15) << 2;
        *(float4*)&sQ[r * 64 + c4] =
            *(const float4*)(Q + base + (size_t)(qb * 64 + r) * DM + c4);
    }

    float acc[4][4];
    float m[4], l[4];
    #pragma unroll
    for (int i = 0; i < 4; i++) {
        m[i] = -1e30f; l[i] = 0.f;
        #pragma unroll
        for (int j = 0; j < 4; j++) acc[i][j] = 0.f;
    }

    for (int kb = 0; kb <= qb; kb++) {
        __syncthreads();  // prior PV reads (and Q writes on first iter) complete
        // load K -> sKP (scalar stores, stride 65), V -> sV
        #pragma unroll
        for (int i = 0; i < 4; i++) {
            int idx = t + i * 256;
            int r = idx >> 4, c4 = (idx & 15) << 2;
            float4 kv = *(const float4*)(K + base + (size_t)(kb * 64 + r) * DM + c4);
            sKP[r * 65 + c4 + 0] = kv.x;
            sKP[r * 65 + c4 + 1] = kv.y;
            sKP[r * 65 + c4 + 2] = kv.z;
            sKP[r * 65 + c4 + 3] = kv.w;
            *(float4*)&sV[r * 64 + c4] =
                *(const float4*)(V + base + (size_t)(kb * 64 + r) * DM + c4);
        }
        __syncthreads();

        // S = (Q K^T) * 1/8
        float s[4][4] = {};
        #pragma unroll 8
        for (int d = 0; d < 64; d++) {
            float qv[4], kv[4];
            #pragma unroll
            for (int i = 0; i < 4; i++) qv[i] = sQ[(r0 + i) * 64 + d];
            #pragma unroll
            for (int j = 0; j < 4; j++) kv[j] = sKP[(c0 + j) * 65 + d];
            #pragma unroll
            for (int i = 0; i < 4; i++)
                #pragma unroll
                for (int j = 0; j < 4; j++)
                    s[i][j] = fmaf(qv[i], kv[j], s[i][j]);
        }
        #pragma unroll
        for (int i = 0; i < 4; i++)
            #pragma unroll
            for (int j = 0; j < 4; j++) s[i][j] *= 0.125f;
        if (kb == qb) {  // causal mask on diagonal tile
            #pragma unroll
            for (int i = 0; i < 4; i++)
                #pragma unroll
                for (int j = 0; j < 4; j++)
                    if (c0 + j > r0 + i) s[i][j] = -1e30f;
        }

        // online softmax update (row groups = 16 lanes within a half-warp)
        float mt[4], mn[4], corr[4], rs[4];
        #pragma unroll
        for (int i = 0; i < 4; i++) {
            mt[i] = fmaxf(fmaxf(s[i][0], s[i][1]), fmaxf(s[i][2], s[i][3]));
            #pragma unroll
            for (int o = 8; o > 0; o >>= 1)
                mt[i] = fmaxf(mt[i], __shfl_xor_sync(0xffffffffu, mt[i], o));
            mn[i]   = fmaxf(m[i], mt[i]);
            corr[i] = __expf(m[i] - mn[i]);
            m[i]    = mn[i];
        }
        float p[4][4];
        #pragma unroll
        for (int i = 0; i < 4; i++) {
            rs[i] = 0.f;
            #pragma unroll
            for (int j = 0; j < 4; j++) {
                p[i][j] = __expf(s[i][j] - mn[i]);
                rs[i] += p[i][j];
            }
            #pragma unroll
            for (int o = 8; o > 0; o >>= 1)
                rs[i] += __shfl_xor_sync(0xffffffffu, rs[i], o);
            l[i] = l[i] * corr[i] + rs[i];
            #pragma unroll
            for (int j = 0; j < 4; j++) acc[i][j] *= corr[i];
        }

        __syncthreads();  // all S reads of K done before overwriting with P
        #pragma unroll
        for (int i = 0; i < 4; i++)
            #pragma unroll
            for (int j = 0; j < 4; j++)
                sKP[(r0 + i) * 65 + c0 + j] = p[i][j];
        __syncthreads();

        // acc += P @ V
        #pragma unroll 8
        for (int c = 0; c < 64; c++) {
            float pv[4];
            #pragma unroll
            for (int i = 0; i < 4; i++) pv[i] = sKP[(r0 + i) * 65 + c];
            float4 vv = *(const float4*)&sV[c * 64 + c0];
            #pragma unroll
            for (int i = 0; i < 4; i++) {
                acc[i][0] = fmaf(pv[i], vv.x, acc[i][0]);
                acc[i][1] = fmaf(pv[i], vv.y, acc[i][1]);
                acc[i][2] = fmaf(pv[i], vv.z, acc[i][2]);
                acc[i][3] = fmaf(pv[i], vv.w, acc[i][3]);
            }
        }
    }

    #pragma unroll
    for (int i = 0; i < 4; i++) {
        float inv = 1.0f / l[i];
        float4 o = make_float4(acc[i][0] * inv, acc[i][1] * inv,
                               acc[i][2] * inv, acc[i][3] * inv);
        *(float4*)(O + base + (size_t)(qb * 64 + r0 + i) * DM + c0) = o;
    }
}

// ---------------- launch ----------------
extern "C" void kernel_launch(void* const* d_in, const int* in_sizes, int n_in,
                              void* d_out, int out_size) {
    const float* H    = (const float*)d_in[0];
    const float* Wq   = (const float*)d_in[1];
    const float* Wk   = (const float*)d_in[2];
    const float* Wv   = (const float*)d_in[3];
    const float* Wo   = (const float*)d_in[4];
    const float* ln1g = (const float*)d_in[5];
    const float* ln1b = (const float*)d_in[6];
    const float* ln2g = (const float*)d_in[7];
    const float* ln2b = (const float*)d_in[8];
    const float* W1   = (const float*)d_in[9];
    const float* b1   = (const float*)d_in[10];
    const float* W2   = (const float*)d_in[11];
    const float* b2   = (const float*)d_in[12];
    float* out = (float*)d_out;

    float *xn, *q, *k, *v, *att, *h1, *mlp;
    cudaGetSymbolAddress((void**)&xn,  g_xn);
    cudaGetSymbolAddress((void**)&q,   g_q);
    cudaGetSymbolAddress((void**)&k,   g_k);
    cudaGetSymbolAddress((void**)&v,   g_v);
    cudaGetSymbolAddress((void**)&att, g_att);
    cudaGetSymbolAddress((void**)&h1,  g_h1);
    cudaGetSymbolAddress((void**)&mlp, g_mlp);

    cudaFuncSetAttribute(attn_kernel, cudaFuncAttributeMaxDynamicSharedMemorySize,
                         ATTN_SMEM);
    cudaFuncSetAttribute(gemm_tf32<0>, cudaFuncAttributeMaxDynamicSharedMemorySize,
                         (int)GEMM_SMEM);
    cudaFuncSetAttribute(gemm_tf32<1>, cudaFuncAttributeMaxDynamicSharedMemorySize,
                         (int)GEMM_SMEM);
    cudaFuncSetAttribute(gemm_tf32<2>, cudaFuncAttributeMaxDynamicSharedMemorySize,
                         (int)GEMM_SMEM);
    cudaFuncSetAttribute(gemm_tf32<3>, cudaFuncAttributeMaxDynamicSharedMemorySize,
                         (int)GEMM_SMEM);

    dim3 gProj(DM / 128, TOK / 128);   // 8 x 32
    dim3 gMlp1(DFF / 128, TOK / 128);  // 32 x 32

    // LN1
    ln_kernel<<<TOK, 256>>>(H, ln1g, ln1b, xn);
    // Q, K, V projections
    gemm_tf32<0><<<gProj, 256, GEMM_SMEM>>>(xn, Wq, nullptr, nullptr, q, TOK, DM, DM);
    gemm_tf32<0><<<gProj, 256, GEMM_SMEM>>>(xn, Wk, nullptr, nullptr, k, TOK, DM, DM);
    gemm_tf32<0><<<gProj, 256, GEMM_SMEM>>>(xn, Wv, nullptr, nullptr, v, TOK, DM, DM);
    // fused causal attention
    attn_kernel<<<dim3(32, 16, 2), 256, ATTN_SMEM>>>(q, k, v, att);
    // O projection + residual
    gemm_tf32<3><<<gProj, 256, GEMM_SMEM>>>(att, Wo, nullptr, H, h1, TOK, DM, DM);
    // LN2
    ln_kernel<<<TOK, 256>>>(h1, ln2g, ln2b, xn);
    // MLP
    gemm_tf32<1><<<gMlp1, 256, GEMM_SMEM>>>(xn, W1, b1, nullptr, mlp, TOK, DFF, DM);
    gemm_tf32<2><<<gProj, 256, GEMM_SMEM>>>(mlp, W2, b2, h1, out, TOK, DM, DFF);
}

// round 5
// speedup vs baseline: 3.3846x; 1.3271x over previous
#include <cuda_runtime.h>
#include <stdint.h>
#include <math.h>

#define TOK 4096
#define DM 1024
#define DFF 4096

// ---------------- scratch (static device globals; no allocs) ----------------
__device__ float g_xn[TOK * DM];           // LN output (reused for LN1 and LN2)
__device__ float g_q[TOK * DM];
__device__ float g_k[TOK * DM];
__device__ float g_v[TOK * DM];
__device__ float g_att[TOK * DM];
__device__ float g_h1[TOK * DM];           // H after attention residual
__device__ float g_mlp[(size_t)TOK * DFF]; // GELU hidden

// ---------------- LayerNorm: one block per row ----------------
__global__ __launch_bounds__(256) void ln_kernel(const float* __restrict__ x,
                                                 const float* __restrict__ g,
                                                 const float* __restrict__ b,
                                                 float* __restrict__ out) {
    int row = blockIdx.x;
    int t = threadIdx.x;
    const float4* xr = (const float4*)(x + (size_t)row * DM);
    float4 v = xr[t];
    float s  = v.x + v.y + v.z + v.w;
    float ss = v.x * v.x + v.y * v.y + v.z * v.z + v.w * v.w;
    #pragma unroll
    for (int o = 16; o > 0; o >>= 1) {
        s  += __shfl_xor_sync(0xffffffffu, s, o);
        ss += __shfl_xor_sync(0xffffffffu, ss, o);
    }
    __shared__ float red[2][8];
    if ((t & 31) == 0) { red[0][t >> 5] = s; red[1][t >> 5] = ss; }
    __syncthreads();
    float ts = 0.f, tss = 0.f;
    #pragma unroll
    for (int i = 0; i < 8; i++) { ts += red[0][i]; tss += red[1][i]; }
    float mu   = ts * (1.0f / DM);
    float var  = tss * (1.0f / DM) - mu * mu;
    float rstd = rsqrtf(var + 1e-5f);
    float4 gv = ((const float4*)g)[t];
    float4 bv = ((const float4*)b)[t];
    float4 o;
    o.x = (v.x - mu) * rstd * gv.x + bv.x;
    o.y = (v.y - mu) * rstd * gv.y + bv.y;
    o.z = (v.z - mu) * rstd * gv.z + bv.z;
    o.w = (v.w - mu) * rstd * gv.w + bv.w;
    ((float4*)(out + (size_t)row * DM))[t] = o;
}

// ---------------- TF32 primitives ----------------
__device__ __forceinline__ uint32_t f2tf32(float x) {
    uint32_t r;
    asm("cvt.rna.tf32.f32 %0, %1;" : "=r"(r) : "f"(x));
    return r;
}

__device__ __forceinline__ void mma_tf32(float c[4],
                                         uint32_t a0, uint32_t a1,
                                         uint32_t a2, uint32_t a3,
                                         uint32_t b0, uint32_t b1) {
    asm volatile(
        "mma.sync.aligned.m16n8k8.row.col.f32.tf32.tf32.f32 "
        "{%0,%1,%2,%3}, {%4,%5,%6,%7}, {%8,%9}, {%0,%1,%2,%3};\n"
        : "+f"(c[0]), "+f"(c[1]), "+f"(c[2]), "+f"(c[3])
        : "r"(a0), "r"(a1), "r"(a2), "r"(a3), "r"(b0), "r"(b1));
}

__device__ __forceinline__ void cp_async16(uint32_t smem, const void* gptr) {
    asm volatile("cp.async.cg.shared.global [%0], [%1], 16;\n"
                 :: "r"(smem), "l"(gptr));
}

// ---------------- TF32 tensor-core GEMM body ----------------
// C[M,N] = A[M,K] @ B[K,N] (+ epilogue)
// EPI: 0 = none, 1 = +bias then exact GELU, 2 = +bias +res, 3 = +res
// Block tile 128x128x32, 8 warps as 2(m) x 4(n); per warp 4x4 m16n8k8 tiles.

#define ASTR 36
#define BSTR 136
#define ASZ (128 * ASTR)
#define BSZ (32 * BSTR)
#define GEMM_SMEM ((ASZ + BSZ) * 2 * sizeof(float))

template <int EPI>
__device__ __forceinline__ void gemm_body(const float* __restrict__ A,
                                          const float* __restrict__ B,
                                          const float* __restrict__ bias,
                                          const float* __restrict__ res,
                                          float* __restrict__ C,
                                          int M, int N, int K, float* sm) {
    uint32_t sbase = (uint32_t)__cvta_generic_to_shared(sm);

    int t = threadIdx.x;
    int bn = blockIdx.x, bm = blockIdx.y;
    int wid = t >> 5, lane = t & 31;
    int wm = wid & 1, wn = wid >> 1;          // 2 x 4 warp grid
    int g = lane >> 2, tig = lane & 3;

    const float* Abase = A + (size_t)(bm * 128) * K;
    const float* Bbase = B + bn * 128;

    auto load_tiles = [&](int k0, int buf) {
        uint32_t sa = sbase + (uint32_t)(buf * (ASZ + BSZ)) * 4u;
        uint32_t sb = sa + (uint32_t)ASZ * 4u;
        const float* Ap = Abase + k0;
        const float* Bp = Bbase + (size_t)k0 * N;
        #pragma unroll
        for (int i = 0; i < 4; i++) {          // A: 128 rows x 32 cols
            int idx = t + i * 256;
            int r = idx >> 3, c4 = (idx & 7) << 2;
            cp_async16(sa + (uint32_t)(r * ASTR + c4) * 4u,
                       Ap + (size_t)r * K + c4);
        }
        #pragma unroll
        for (int i = 0; i < 4; i++) {          // B: 32 rows x 128 cols
            int idx = t + i * 256;
            int r = idx >> 5, c4 = (idx & 31) << 2;
            cp_async16(sb + (uint32_t)(r * BSTR + c4) * 4u,
                       Bp + (size_t)r * N + c4);
        }
        asm volatile("cp.async.commit_group;\n");
    };

    float acc[4][4][4];
    #pragma unroll
    for (int i = 0; i < 4; i++)
        #pragma unroll
        for (int j = 0; j < 4; j++)
            #pragma unroll
            for (int r = 0; r < 4; r++) acc[i][j][r] = 0.f;

    load_tiles(0, 0);
    int NC = K >> 5;
    for (int c = 0; c < NC; c++) {
        asm volatile("cp.async.wait_group 0;\n");
        __syncthreads();
        if (c + 1 < NC) load_tiles((c + 1) << 5, (c + 1) & 1);

        const float* a = sm + (c & 1) * (ASZ + BSZ);
        const float* b = a + ASZ;

        #pragma unroll
        for (int ks = 0; ks < 4; ks++) {
            int kc = ks * 8;
            uint32_t af[4][4], bf[4][2];
            #pragma unroll
            for (int mt = 0; mt < 4; mt++) {
                int r = wm * 64 + mt * 16 + g;
                af[mt][0] = f2tf32(a[r * ASTR + kc + tig]);
                af[mt][1] = f2tf32(a[(r + 8) * ASTR + kc + tig]);
                af[mt][2] = f2tf32(a[r * ASTR + kc + tig + 4]);
                af[mt][3] = f2tf32(a[(r + 8) * ASTR + kc + tig + 4]);
            }
            #pragma unroll
            for (int nt = 0; nt < 4; nt++) {
                int cn = wn * 32 + nt * 8 + g;
                bf[nt][0] = f2tf32(b[(kc + tig) * BSTR + cn]);
                bf[nt][1] = f2tf32(b[(kc + tig + 4) * BSTR + cn]);
            }
            #pragma unroll
            for (int mt = 0; mt < 4; mt++)
                #pragma unroll
                for (int nt = 0; nt < 4; nt++)
                    mma_tf32(acc[mt][nt], af[mt][0], af[mt][1], af[mt][2],
                             af[mt][3], bf[nt][0], bf[nt][1]);
        }
        __syncthreads();
    }

    int row0 = bm * 128 + wm * 64;
    int col0 = bn * 128 + wn * 32;
    #pragma unroll
    for (int mt = 0; mt < 4; mt++) {
        #pragma unroll
        for (int half = 0; half < 2; half++) {
            int r = row0 + mt * 16 + half * 8 + g;
            size_t rb = (size_t)r * N;
            #pragma unroll
            for (int nt = 0; nt < 4; nt++) {
                int cn = col0 + nt * 8 + tig * 2;
                float x0 = acc[mt][nt][half * 2];
                float x1 = acc[mt][nt][half * 2 + 1];
                if (EPI == 1) {
                    x0 += bias[cn];
                    x1 += bias[cn + 1];
                    x0 = 0.5f * x0 * (1.0f + erff(x0 * 0.70710678118654752f));
                    x1 = 0.5f * x1 * (1.0f + erff(x1 * 0.70710678118654752f));
                } else if (EPI == 2) {
                    x0 += bias[cn] + res[rb + cn];
                    x1 += bias[cn + 1] + res[rb + cn + 1];
                } else if (EPI == 3) {
                    x0 += res[rb + cn];
                    x1 += res[rb + cn + 1];
                }
                *(float2*)(C + rb + cn) = make_float2(x0, x1);
            }
        }
    }
}

template <int EPI>
__global__ __launch_bounds__(256) void gemm_tf32(const float* __restrict__ A,
                                                 const float* __restrict__ B,
                                                 const float* __restrict__ bias,
                                                 const float* __restrict__ res,
                                                 float* __restrict__ C,
                                                 int M, int N, int K) {
    extern __shared__ float sm[];
    gemm_body<EPI>(A, B, bias, res, C, M, N, K, sm);
}

// Fused Q/K/V projection: blockIdx.z selects weight + destination.
__global__ __launch_bounds__(256) void gemm_qkv(const float* __restrict__ A,
                                                const float* __restrict__ Wq,
                                                const float* __restrict__ Wk,
                                                const float* __restrict__ Wv,
                                                float* __restrict__ q,
                                                float* __restrict__ k,
                                                float* __restrict__ v,
                                                int M, int N, int K) {
    extern __shared__ float sm[];
    const float* B = (blockIdx.z == 0) ? Wq : (blockIdx.z == 1) ? Wk : Wv;
    float* C = (blockIdx.z == 0) ? q : (blockIdx.z == 1) ? k : v;
    gemm_body<0>(A, B, nullptr, nullptr, C, M, N, K, sm);
}

// ---------------- TF32 tensor-core causal flash attention ----------------
// Q,K,V,O all [4096,1024] = [b*2048+t, h*64+d]. Block = (q-tile 64, head, batch).
// 4 warps x 16 q-rows. Q tf32 fragments live in registers across all key tiles.
// smem: sK [64key][stride], sVt [64d][stride] (V transposed), sP (Q staging, then
// per-warp P staging; each warp reads only its own 16 rows -> __syncwarp only).
#define ATSTR 68
#define ATTN_SMEM (3 * 64 * ATSTR * 4)

__global__ __launch_bounds__(128) void attn_tc(const float* __restrict__ Q,
                                               const float* __restrict__ K,
                                               const float* __restrict__ V,
                                               float* __restrict__ O) {
    extern __shared__ float sm[];
    float* sK  = sm;
    float* sVt = sm + 64 * ATSTR;
    float* sP  = sm + 2 * 64 * ATSTR;   // Q staging, then P staging

    int qb = blockIdx.x, h = blockIdx.y, bb = blockIdx.z;
    int t = threadIdx.x;
    int w = t >> 5, lane = t & 31;
    int g = lane >> 2, tig = lane & 3;
    int row = w * 16 + g;               // local q row (also handles row+8)
    size_t base = ((size_t)bb * 2048) * DM + (size_t)h * 64;

    // stage Q tile -> sP
    #pragma unroll
    for (int i = 0; i < 8; i++) {
        int idx = t + i * 128;
        int r = idx >> 4, c4 = (idx & 15) << 2;
        *(float4*)&sP[r * ATSTR + c4] =
            *(const float4*)(Q + base + (size_t)(qb * 64 + r) * DM + c4);
    }
    __syncthreads();

    // extract Q fragments (held in registers for the whole kernel)
    uint32_t qf[8][4];
    #pragma unroll
    for (int ks = 0; ks < 8; ks++) {
        int kc = ks * 8;
        qf[ks][0] = f2tf32(sP[row * ATSTR + kc + tig]);
        qf[ks][1] = f2tf32(sP[(row + 8) * ATSTR + kc + tig]);
        qf[ks][2] = f2tf32(sP[row * ATSTR + kc + tig + 4]);
        qf[ks][3] = f2tf32(sP[(row + 8) * ATSTR + kc + tig + 4]);
    }

    float oa[8][4];
    #pragma unroll
    for (int nt = 0; nt < 8; nt++)
        #pragma unroll
        for (int r = 0; r < 4; r++) oa[nt][r] = 0.f;
    float m0 = -1e30f, m1 = -1e30f, l0 = 0.f, l1 = 0.f;

    for (int kb = 0; kb <= qb; kb++) {
        __syncthreads();  // prior PV reads of sVt done; Q extraction done (kb==0)
        // load K tile (row-major) and V tile (transposed)
        #pragma unroll
        for (int i = 0; i < 8; i++) {
            int idx = t + i * 128;
            int r = idx >> 4, c4 = (idx & 15) << 2;
            size_t goff = base + (size_t)(kb * 64 + r) * DM + c4;
            *(float4*)&sK[r * ATSTR + c4] = *(const float4*)(K + goff);
            float4 vv = *(const float4*)(V + goff);
            sVt[(c4 + 0) * ATSTR + r] = vv.x;
            sVt[(c4 + 1) * ATSTR + r] = vv.y;
            sVt[(c4 + 2) * ATSTR + r] = vv.z;
            sVt[(c4 + 3) * ATSTR + r] = vv.w;
        }
        __syncthreads();

        // S = Q K^T  (tf32 mma), rows [w*16, w*16+16), all 64 keys
        float s[8][4];
        #pragma unroll
        for (int nt = 0; nt < 8; nt++)
            #pragma unroll
            for (int r = 0; r < 4; r++) s[nt][r] = 0.f;
        #pragma unroll
        for (int ks = 0; ks < 8; ks++) {
            int kc = ks * 8;
            #pragma unroll
            for (int nt = 0; nt < 8; nt++) {
                int cn = nt * 8 + g;
                uint32_t b0 = f2tf32(sK[cn * ATSTR + kc + tig]);
                uint32_t b1 = f2tf32(sK[cn * ATSTR + kc + tig + 4]);
                mma_tf32(s[nt], qf[ks][0], qf[ks][1], qf[ks][2], qf[ks][3],
                         b0, b1);
            }
        }
        // scale + causal mask (diagonal tile only)
        #pragma unroll
        for (int nt = 0; nt < 8; nt++)
            #pragma unroll
            for (int r = 0; r < 4; r++) s[nt][r] *= 0.125f;
        if (kb == qb) {
            int q0 = row, q1 = row + 8;       // local indices; same tile base
            #pragma unroll
            for (int nt = 0; nt < 8; nt++) {
                int c0 = nt * 8 + 2 * tig, c1 = c0 + 1;
                if (c0 > q0) s[nt][0] = -1e30f;
                if (c1 > q0) s[nt][1] = -1e30f;
                if (c0 > q1) s[nt][2] = -1e30f;
                if (c1 > q1) s[nt][3] = -1e30f;
            }
        }

        // online softmax (rows: `row` via s[][0,1], `row+8` via s[][2,3])
        float mt0 = -1e30f, mt1 = -1e30f;
        #pragma unroll
        for (int nt = 0; nt < 8; nt++) {
            mt0 = fmaxf(mt0, fmaxf(s[nt][0], s[nt][1]));
            mt1 = fmaxf(mt1, fmaxf(s[nt][2], s[nt][3]));
        }
        #pragma unroll
        for (int o = 1; o <= 2; o <<= 1) {
            mt0 = fmaxf(mt0, __shfl_xor_sync(0xffffffffu, mt0, o));
            mt1 = fmaxf(mt1, __shfl_xor_sync(0xffffffffu, mt1, o));
        }
        float mn0 = fmaxf(m0, mt0), mn1 = fmaxf(m1, mt1);
        float corr0 = __expf(m0 - mn0), corr1 = __expf(m1 - mn1);
        m0 = mn0; m1 = mn1;
        float rs0 = 0.f, rs1 = 0.f;
        #pragma unroll
        for (int nt = 0; nt < 8; nt++) {
            s[nt][0] = __expf(s[nt][0] - mn0);
            s[nt][1] = __expf(s[nt][1] - mn0);
            s[nt][2] = __expf(s[nt][2] - mn1);
            s[nt][3] = __expf(s[nt][3] - mn1);
            rs0 += s[nt][0] + s[nt][1];
            rs1 += s[nt][2] + s[nt][3];
        }
        #pragma unroll
        for (int o = 1; o <= 2; o <<= 1) {
            rs0 += __shfl_xor_sync(0xffffffffu, rs0, o);
            rs1 += __shfl_xor_sync(0xffffffffu, rs1, o);
        }
        l0 = l0 * corr0 + rs0;
        l1 = l1 * corr1 + rs1;
        #pragma unroll
        for (int nt = 0; nt < 8; nt++) {
            oa[nt][0] *= corr0; oa[nt][1] *= corr0;
            oa[nt][2] *= corr1; oa[nt][3] *= corr1;
        }

        // stage P (each warp writes/reads only its own 16 rows)
        #pragma unroll
        for (int nt = 0; nt < 8; nt++) {
            int cc = nt * 8 + 2 * tig;
            *(float2*)&sP[row * ATSTR + cc]       = make_float2(s[nt][0], s[nt][1]);
            *(float2*)&sP[(row + 8) * ATSTR + cc] = make_float2(s[nt][2], s[nt][3]);
        }
        __syncwarp();

        // O += P @ V   (A = P rows, B = V^T col-major -> sVt)
        #pragma unroll
        for (int ks = 0; ks < 8; ks++) {
            int kc = ks * 8;
            uint32_t a0 = f2tf32(sP[row * ATSTR + kc + tig]);
            uint32_t a1 = f2tf32(sP[(row + 8) * ATSTR + kc + tig]);
            uint32_t a2 = f2tf32(sP[row * ATSTR + kc + tig + 4]);
            uint32_t a3 = f2tf32(sP[(row + 8) * ATSTR + kc + tig + 4]);
            #pragma unroll
            for (int nt = 0; nt < 8; nt++) {
                int cn = nt * 8 + g;
                uint32_t b0 = f2tf32(sVt[cn * ATSTR + kc + tig]);
                uint32_t b1 = f2tf32(sVt[cn * ATSTR + kc + tig + 4]);
                mma_tf32(oa[nt], a0, a1, a2, a3, b0, b1);
            }
        }
        __syncwarp();   // P reads complete before next-tile reuse
    }

    // epilogue
    float inv0 = 1.0f / l0, inv1 = 1.0f / l1;
    size_t r0 = base + (size_t)(qb * 64 + row) * DM;
    size_t r1 = base + (size_t)(qb * 64 + row + 8) * DM;
    #pragma unroll
    for (int nt = 0; nt < 8; nt++) {
        int cc = nt * 8 + 2 * tig;
        *(float2*)(O + r0 + cc) = make_float2(oa[nt][0] * inv0, oa[nt][1] * inv0);
        *(float2*)(O + r1 + cc) = make_float2(oa[nt][2] * inv1, oa[nt][3] * inv1);
    }
}

// ---------------- launch ----------------
extern "C" void kernel_launch(void* const* d_in, const int* in_sizes, int n_in,
                              void* d_out, int out_size) {
    const float* H    = (const float*)d_in[0];
    const float* Wq   = (const float*)d_in[1];
    const float* Wk   = (const float*)d_in[2];
    const float* Wv   = (const float*)d_in[3];
    const float* Wo   = (const float*)d_in[4];
    const float* ln1g = (const float*)d_in[5];
    const float* ln1b = (const float*)d_in[6];
    const float* ln2g = (const float*)d_in[7];
    const float* ln2b = (const float*)d_in[8];
    const float* W1   = (const float*)d_in[9];
    const float* b1   = (const float*)d_in[10];
    const float* W2   = (const float*)d_in[11];
    const float* b2   = (const float*)d_in[12];
    float* out = (float*)d_out;

    float *xn, *q, *k, *v, *att, *h1, *mlp;
    cudaGetSymbolAddress((void**)&xn,  g_xn);
    cudaGetSymbolAddress((void**)&q,   g_q);
    cudaGetSymbolAddress((void**)&k,   g_k);
    cudaGetSymbolAddress((void**)&v,   g_v);
    cudaGetSymbolAddress((void**)&att, g_att);
    cudaGetSymbolAddress((void**)&h1,  g_h1);
    cudaGetSymbolAddress((void**)&mlp, g_mlp);

    cudaFuncSetAttribute(attn_tc, cudaFuncAttributeMaxDynamicSharedMemorySize,
                         ATTN_SMEM);
    cudaFuncSetAttribute(gemm_qkv, cudaFuncAttributeMaxDynamicSharedMemorySize,
                         (int)GEMM_SMEM);
    cudaFuncSetAttribute(gemm_tf32<1>, cudaFuncAttributeMaxDynamicSharedMemorySize,
                         (int)GEMM_SMEM);
    cudaFuncSetAttribute(gemm_tf32<2>, cudaFuncAttributeMaxDynamicSharedMemorySize,
                         (int)GEMM_SMEM);
    cudaFuncSetAttribute(gemm_tf32<3>, cudaFuncAttributeMaxDynamicSharedMemorySize,
                         (int)GEMM_SMEM);

    dim3 gProj(DM / 128, TOK / 128);        // 8 x 32
    dim3 gQkv(DM / 128, TOK / 128, 3);      // 8 x 32 x 3
    dim3 gMlp1(DFF / 128, TOK / 128);       // 32 x 32

    // LN1
    ln_kernel<<<TOK, 256>>>(H, ln1g, ln1b, xn);
    // fused Q, K, V projections
    gemm_qkv<<<gQkv, 256, GEMM_SMEM>>>(xn, Wq, Wk, Wv, q, k, v, TOK, DM, DM);
    // fused causal attention (tensor cores)
    attn_tc<<<dim3(32, 16, 2), 128, ATTN_SMEM>>>(q, k, v, att);
    // O projection + residual
    gemm_tf32<3><<<gProj, 256, GEMM_SMEM>>>(att, Wo, nullptr, H, h1, TOK, DM, DM);
    // LN2
    ln_kernel<<<TOK, 256>>>(h1, ln2g, ln2b, xn);
    // MLP
    gemm_tf32<1><<<gMlp1, 256, GEMM_SMEM>>>(xn, W1, b1, nullptr, mlp, TOK, DFF, DM);
    gemm_tf32<2><<<gProj, 256, GEMM_SMEM>>>(mlp, W2, b2, h1, out, TOK, DM, DFF);
}

// round 6
// speedup vs baseline: 3.6972x; 1.0924x over previous
#include <cuda_runtime.h>
#include <stdint.h>
#include <math.h>

#define TOK 4096
#define DM 1024
#define DFF 4096

// ---------------- scratch (static device globals; no allocs) ----------------
__device__ float g_xn[TOK * DM];           // LN output (tf32-rounded)
__device__ float g_q[TOK * DM];
__device__ float g_k[TOK * DM];
__device__ float g_v[TOK * DM];
__device__ float g_att[TOK * DM];
__device__ float g_h1[TOK * DM];           // H after attention residual (exact)
__device__ float g_mlp[(size_t)TOK * DFF]; // GELU hidden (tf32-rounded)
__device__ float g_wqkvo[4 * DM * DM];     // tf32-rounded weights
__device__ float g_w1r[(size_t)DM * DFF];
__device__ float g_w2r[(size_t)DFF * DM];

// ---------------- TF32 primitives ----------------
__device__ __forceinline__ uint32_t f2tf32(float x) {
    uint32_t r;
    asm("cvt.rna.tf32.f32 %0, %1;" : "=r"(r) : "f"(x));
    return r;
}
__device__ __forceinline__ float roundtf(float x) {
    return __uint_as_float(f2tf32(x));
}

__device__ __forceinline__ void mma_tf32(float c[4],
                                         uint32_t a0, uint32_t a1,
                                         uint32_t a2, uint32_t a3,
                                         uint32_t b0, uint32_t b1) {
    asm volatile(
        "mma.sync.aligned.m16n8k8.row.col.f32.tf32.tf32.f32 "
        "{%0,%1,%2,%3}, {%4,%5,%6,%7}, {%8,%9}, {%0,%1,%2,%3};\n"
        : "+f"(c[0]), "+f"(c[1]), "+f"(c[2]), "+f"(c[3])
        : "r"(a0), "r"(a1), "r"(a2), "r"(a3), "r"(b0), "r"(b1));
}

__device__ __forceinline__ void cp_async16(uint32_t smem, const void* gptr) {
    asm volatile("cp.async.cg.shared.global [%0], [%1], 16;\n"
                 :: "r"(smem), "l"(gptr));
}

// ---------------- tf32 rounding pass (weights, once per launch) ----------------
__global__ __launch_bounds__(256) void round_kernel(const float4* __restrict__ src,
                                                    float4* __restrict__ dst,
                                                    int n4) {
    int i = blockIdx.x * 256 + threadIdx.x;
    if (i < n4) {
        float4 v = src[i];
        v.x = roundtf(v.x); v.y = roundtf(v.y);
        v.z = roundtf(v.z); v.w = roundtf(v.w);
        dst[i] = v;
    }
}

// ---------------- LayerNorm: one block per row (tf32-rounded output) --------
__global__ __launch_bounds__(256) void ln_kernel(const float* __restrict__ x,
                                                 const float* __restrict__ g,
                                                 const float* __restrict__ b,
                                                 float* __restrict__ out) {
    int row = blockIdx.x;
    int t = threadIdx.x;
    const float4* xr = (const float4*)(x + (size_t)row * DM);
    float4 v = xr[t];
    float s  = v.x + v.y + v.z + v.w;
    float ss = v.x * v.x + v.y * v.y + v.z * v.z + v.w * v.w;
    #pragma unroll
    for (int o = 16; o > 0; o >>= 1) {
        s  += __shfl_xor_sync(0xffffffffu, s, o);
        ss += __shfl_xor_sync(0xffffffffu, ss, o);
    }
    __shared__ float red[2][8];
    if ((t & 31) == 0) { red[0][t >> 5] = s; red[1][t >> 5] = ss; }
    __syncthreads();
    float ts = 0.f, tss = 0.f;
    #pragma unroll
    for (int i = 0; i < 8; i++) { ts += red[0][i]; tss += red[1][i]; }
    float mu   = ts * (1.0f / DM);
    float var  = tss * (1.0f / DM) - mu * mu;
    float rstd = rsqrtf(var + 1e-5f);
    float4 gv = ((const float4*)g)[t];
    float4 bv = ((const float4*)b)[t];
    float4 o;
    o.x = roundtf((v.x - mu) * rstd * gv.x + bv.x);
    o.y = roundtf((v.y - mu) * rstd * gv.y + bv.y);
    o.z = roundtf((v.z - mu) * rstd * gv.z + bv.z);
    o.w = roundtf((v.w - mu) * rstd * gv.w + bv.w);
    ((float4*)(out + (size_t)row * DM))[t] = o;
}

// ---------------- TF32 tensor-core GEMM body ----------------
// C[M,N] = A[M,K] @ B[K,N] (+ epilogue). A and B MUST be tf32-pre-rounded.
// EPI: 0 = none, 1 = +bias then exact GELU, 2 = +bias +res, 3 = +res
// RND: round stored C to tf32 (for outputs consumed as mma operands)
// Block tile 128x128x32, 8 warps as 2(m) x 4(n); per warp 4x4 m16n8k8 tiles.

#define ASTR 36
#define BSTR 136
#define ASZ (128 * ASTR)
#define BSZ (32 * BSTR)
#define GEMM_SMEM ((ASZ + BSZ) * 2 * sizeof(float))

template <int EPI, int RND>
__device__ __forceinline__ void gemm_body(const float* __restrict__ A,
                                          const float* __restrict__ B,
                                          const float* __restrict__ bias,
                                          const float* __restrict__ res,
                                          float* __restrict__ C,
                                          int M, int N, int K, float* sm) {
    uint32_t sbase = (uint32_t)__cvta_generic_to_shared(sm);

    int t = threadIdx.x;
    int bn = blockIdx.x, bm = blockIdx.y;
    int wid = t >> 5, lane = t & 31;
    int wm = wid & 1, wn = wid >> 1;          // 2 x 4 warp grid
    int g = lane >> 2, tig = lane & 3;

    const float* Abase = A + (size_t)(bm * 128) * K;
    const float* Bbase = B + bn * 128;

    auto load_tiles = [&](int k0, int buf) {
        uint32_t sa = sbase + (uint32_t)(buf * (ASZ + BSZ)) * 4u;
        uint32_t sb = sa + (uint32_t)ASZ * 4u;
        const float* Ap = Abase + k0;
        const float* Bp = Bbase + (size_t)k0 * N;
        #pragma unroll
        for (int i = 0; i < 4; i++) {          // A: 128 rows x 32 cols
            int idx = t + i * 256;
            int r = idx >> 3, c4 = (idx & 7) << 2;
            cp_async16(sa + (uint32_t)(r * ASTR + c4) * 4u,
                       Ap + (size_t)r * K + c4);
        }
        #pragma unroll
        for (int i = 0; i < 4; i++) {          // B: 32 rows x 128 cols
            int idx = t + i * 256;
            int r = idx >> 5, c4 = (idx & 31) << 2;
            cp_async16(sb + (uint32_t)(r * BSTR + c4) * 4u,
                       Bp + (size_t)r * N + c4);
        }
        asm volatile("cp.async.commit_group;\n");
    };

    float acc[4][4][4];
    #pragma unroll
    for (int i = 0; i < 4; i++)
        #pragma unroll
        for (int j = 0; j < 4; j++)
            #pragma unroll
            for (int r = 0; r < 4; r++) acc[i][j][r] = 0.f;

    load_tiles(0, 0);
    int NC = K >> 5;
    for (int c = 0; c < NC; c++) {
        asm volatile("cp.async.wait_group 0;\n");
        __syncthreads();
        if (c + 1 < NC) load_tiles((c + 1) << 5, (c + 1) & 1);

        const float* a = sm + (c & 1) * (ASZ + BSZ);
        const float* b = a + ASZ;

        #pragma unroll
        for (int ks = 0; ks < 4; ks++) {
            int kc = ks * 8;
            uint32_t af[4][4], bf[4][2];
            #pragma unroll
            for (int mt = 0; mt < 4; mt++) {
                int r = wm * 64 + mt * 16 + g;
                af[mt][0] = __float_as_uint(a[r * ASTR + kc + tig]);
                af[mt][1] = __float_as_uint(a[(r + 8) * ASTR + kc + tig]);
                af[mt][2] = __float_as_uint(a[r * ASTR + kc + tig + 4]);
                af[mt][3] = __float_as_uint(a[(r + 8) * ASTR + kc + tig + 4]);
            }
            #pragma unroll
            for (int nt = 0; nt < 4; nt++) {
                int cn = wn * 32 + nt * 8 + g;
                bf[nt][0] = __float_as_uint(b[(kc + tig) * BSTR + cn]);
                bf[nt][1] = __float_as_uint(b[(kc + tig + 4) * BSTR + cn]);
            }
            #pragma unroll
            for (int mt = 0; mt < 4; mt++)
                #pragma unroll
                for (int nt = 0; nt < 4; nt++)
                    mma_tf32(acc[mt][nt], af[mt][0], af[mt][1], af[mt][2],
                             af[mt][3], bf[nt][0], bf[nt][1]);
        }
        __syncthreads();
    }

    int row0 = bm * 128 + wm * 64;
    int col0 = bn * 128 + wn * 32;
    #pragma unroll
    for (int mt = 0; mt < 4; mt++) {
        #pragma unroll
        for (int half = 0; half < 2; half++) {
            int r = row0 + mt * 16 + half * 8 + g;
            size_t rb = (size_t)r * N;
            #pragma unroll
            for (int nt = 0; nt < 4; nt++) {
                int cn = col0 + nt * 8 + tig * 2;
                float x0 = acc[mt][nt][half * 2];
                float x1 = acc[mt][nt][half * 2 + 1];
                if (EPI == 1) {
                    x0 += bias[cn];
                    x1 += bias[cn + 1];
                    x0 = 0.5f * x0 * (1.0f + erff(x0 * 0.70710678118654752f));
                    x1 = 0.5f * x1 * (1.0f + erff(x1 * 0.70710678118654752f));
                } else if (EPI == 2) {
                    x0 += bias[cn] + res[rb + cn];
                    x1 += bias[cn + 1] + res[rb + cn + 1];
                } else if (EPI == 3) {
                    x0 += res[rb + cn];
                    x1 += res[rb + cn + 1];
                }
                if (RND) { x0 = roundtf(x0); x1 = roundtf(x1); }
                *(float2*)(C + rb + cn) = make_float2(x0, x1);
            }
        }
    }
}

template <int EPI, int RND>
__global__ __launch_bounds__(256) void gemm_tf32(const float* __restrict__ A,
                                                 const float* __restrict__ B,
                                                 const float* __restrict__ bias,
                                                 const float* __restrict__ res,
                                                 float* __restrict__ C,
                                                 int M, int N, int K) {
    extern __shared__ float sm[];
    gemm_body<EPI, RND>(A, B, bias, res, C, M, N, K, sm);
}

// Fused Q/K/V projection: blockIdx.z selects weight + destination.
__global__ __launch_bounds__(256) void gemm_qkv(const float* __restrict__ A,
                                                const float* __restrict__ W,
                                                float* __restrict__ q,
                                                float* __restrict__ k,
                                                float* __restrict__ v,
                                                int M, int N, int K) {
    extern __shared__ float sm[];
    const float* B = W + (size_t)blockIdx.z * DM * DM;
    float* C = (blockIdx.z == 0) ? q : (blockIdx.z == 1) ? k : v;
    gemm_body<0, 1>(A, B, nullptr, nullptr, C, M, N, K, sm);
}

// ---------------- TF32 tensor-core causal flash attention ----------------
// Q,K,V pre-rounded to tf32; P fed raw (<=1 ulp_tf32 effect). Output rounded.
#define ATSTR 68
#define ATTN_SMEM (3 * 64 * ATSTR * 4)

__global__ __launch_bounds__(128) void attn_tc(const float* __restrict__ Q,
                                               const float* __restrict__ K,
                                               const float* __restrict__ V,
                                               float* __restrict__ O) {
    extern __shared__ float sm[];
    float* sK  = sm;
    float* sVt = sm + 64 * ATSTR;
    float* sP  = sm + 2 * 64 * ATSTR;   // Q staging, then P staging

    int qb = blockIdx.x, h = blockIdx.y, bb = blockIdx.z;
    int t = threadIdx.x;
    int w = t >> 5, lane = t & 31;
    int g = lane >> 2, tig = lane & 3;
    int row = w * 16 + g;               // local q row (also handles row+8)
    size_t base = ((size_t)bb * 2048) * DM + (size_t)h * 64;

    // stage Q tile -> sP
    #pragma unroll
    for (int i = 0; i < 8; i++) {
        int idx = t + i * 128;
        int r = idx >> 4, c4 = (idx & 15) << 2;
        *(float4*)&sP[r * ATSTR + c4] =
            *(const float4*)(Q + base + (size_t)(qb * 64 + r) * DM + c4);
    }
    __syncthreads();

    // extract Q fragments (held in registers for the whole kernel)
    uint32_t qf[8][4];
    #pragma unroll
    for (int ks = 0; ks < 8; ks++) {
        int kc = ks * 8;
        qf[ks][0] = __float_as_uint(sP[row * ATSTR + kc + tig]);
        qf[ks][1] = __float_as_uint(sP[(row + 8) * ATSTR + kc + tig]);
        qf[ks][2] = __float_as_uint(sP[row * ATSTR + kc + tig + 4]);
        qf[ks][3] = __float_as_uint(sP[(row + 8) * ATSTR + kc + tig + 4]);
    }

    float oa[8][4];
    #pragma unroll
    for (int nt = 0; nt < 8; nt++)
        #pragma unroll
        for (int r = 0; r < 4; r++) oa[nt][r] = 0.f;
    float m0 = -1e30f, m1 = -1e30f, l0 = 0.f, l1 = 0.f;

    for (int kb = 0; kb <= qb; kb++) {
        __syncthreads();  // prior PV reads of sVt done; Q extraction done (kb==0)
        #pragma unroll
        for (int i = 0; i < 8; i++) {
            int idx = t + i * 128;
            int r = idx >> 4, c4 = (idx & 15) << 2;
            size_t goff = base + (size_t)(kb * 64 + r) * DM + c4;
            *(float4*)&sK[r * ATSTR + c4] = *(const float4*)(K + goff);
            float4 vv = *(const float4*)(V + goff);
            sVt[(c4 + 0) * ATSTR + r] = vv.x;
            sVt[(c4 + 1) * ATSTR + r] = vv.y;
            sVt[(c4 + 2) * ATSTR + r] = vv.z;
            sVt[(c4 + 3) * ATSTR + r] = vv.w;
        }
        __syncthreads();

        // S = Q K^T
        float s[8][4];
        #pragma unroll
        for (int nt = 0; nt < 8; nt++)
            #pragma unroll
            for (int r = 0; r < 4; r++) s[nt][r] = 0.f;
        #pragma unroll
        for (int ks = 0; ks < 8; ks++) {
            int kc = ks * 8;
            #pragma unroll
            for (int nt = 0; nt < 8; nt++) {
                int cn = nt * 8 + g;
                uint32_t b0 = __float_as_uint(sK[cn * ATSTR + kc + tig]);
                uint32_t b1 = __float_as_uint(sK[cn * ATSTR + kc + tig + 4]);
                mma_tf32(s[nt], qf[ks][0], qf[ks][1], qf[ks][2], qf[ks][3],
                         b0, b1);
            }
        }
        #pragma unroll
        for (int nt = 0; nt < 8; nt++)
            #pragma unroll
            for (int r = 0; r < 4; r++) s[nt][r] *= 0.125f;
        if (kb == qb) {
            int q0 = row, q1 = row + 8;
            #pragma unroll
            for (int nt = 0; nt < 8; nt++) {
                int c0 = nt * 8 + 2 * tig, c1 = c0 + 1;
                if (c0 > q0) s[nt][0] = -1e30f;
                if (c1 > q0) s[nt][1] = -1e30f;
                if (c0 > q1) s[nt][2] = -1e30f;
                if (c1 > q1) s[nt][3] = -1e30f;
            }
        }

        // online softmax
        float mt0 = -1e30f, mt1 = -1e30f;
        #pragma unroll
        for (int nt = 0; nt < 8; nt++) {
            mt0 = fmaxf(mt0, fmaxf(s[nt][0], s[nt][1]));
            mt1 = fmaxf(mt1, fmaxf(s[nt][2], s[nt][3]));
        }
        #pragma unroll
        for (int o = 1; o <= 2; o <<= 1) {
            mt0 = fmaxf(mt0, __shfl_xor_sync(0xffffffffu, mt0, o));
            mt1 = fmaxf(mt1, __shfl_xor_sync(0xffffffffu, mt1, o));
        }
        float mn0 = fmaxf(m0, mt0), mn1 = fmaxf(m1, mt1);
        float corr0 = __expf(m0 - mn0), corr1 = __expf(m1 - mn1);
        m0 = mn0; m1 = mn1;
        float rs0 = 0.f, rs1 = 0.f;
        #pragma unroll
        for (int nt = 0; nt < 8; nt++) {
            s[nt][0] = __expf(s[nt][0] - mn0);
            s[nt][1] = __expf(s[nt][1] - mn0);
            s[nt][2] = __expf(s[nt][2] - mn1);
            s[nt][3] = __expf(s[nt][3] - mn1);
            rs0 += s[nt][0] + s[nt][1];
            rs1 += s[nt][2] + s[nt][3];
        }
        #pragma unroll
        for (int o = 1; o <= 2; o <<= 1) {
            rs0 += __shfl_xor_sync(0xffffffffu, rs0, o);
            rs1 += __shfl_xor_sync(0xffffffffu, rs1, o);
        }
        l0 = l0 * corr0 + rs0;
        l1 = l1 * corr1 + rs1;
        #pragma unroll
        for (int nt = 0; nt < 8; nt++) {
            oa[nt][0] *= corr0; oa[nt][1] *= corr0;
            oa[nt][2] *= corr1; oa[nt][3] *= corr1;
        }

        // stage P (each warp writes/reads only its own 16 rows)
        #pragma unroll
        for (int nt = 0; nt < 8; nt++) {
            int cc = nt * 8 + 2 * tig;
            *(float2*)&sP[row * ATSTR + cc]       = make_float2(s[nt][0], s[nt][1]);
            *(float2*)&sP[(row + 8) * ATSTR + cc] = make_float2(s[nt][2], s[nt][3]);
        }
        __syncwarp();

        // O += P @ V
        #pragma unroll
        for (int ks = 0; ks < 8; ks++) {
            int kc = ks * 8;
            uint32_t a0 = __float_as_uint(sP[row * ATSTR + kc + tig]);
            uint32_t a1 = __float_as_uint(sP[(row + 8) * ATSTR + kc + tig]);
            uint32_t a2 = __float_as_uint(sP[row * ATSTR + kc + tig + 4]);
            uint32_t a3 = __float_as_uint(sP[(row + 8) * ATSTR + kc + tig + 4]);
            #pragma unroll
            for (int nt = 0; nt < 8; nt++) {
                int cn = nt * 8 + g;
                uint32_t b0 = __float_as_uint(sVt[cn * ATSTR + kc + tig]);
                uint32_t b1 = __float_as_uint(sVt[cn * ATSTR + kc + tig + 4]);
                mma_tf32(oa[nt], a0, a1, a2, a3, b0, b1);
            }
        }
        __syncwarp();   // P reads complete before next-tile reuse
    }

    // epilogue (rounded: att feeds the Wo GEMM as an mma operand)
    float inv0 = 1.0f / l0, inv1 = 1.0f / l1;
    size_t r0 = base + (size_t)(qb * 64 + row) * DM;
    size_t r1 = base + (size_t)(qb * 64 + row + 8) * DM;
    #pragma unroll
    for (int nt = 0; nt < 8; nt++) {
        int cc = nt * 8 + 2 * tig;
        *(float2*)(O + r0 + cc) = make_float2(roundtf(oa[nt][0] * inv0),
                                              roundtf(oa[nt][1] * inv0));
        *(float2*)(O + r1 + cc) = make_float2(roundtf(oa[nt][2] * inv1),
                                              roundtf(oa[nt][3] * inv1));
    }
}

// ---------------- launch ----------------
extern "C" void kernel_launch(void* const* d_in, const int* in_sizes, int n_in,
                              void* d_out, int out_size) {
    const float* H    = (const float*)d_in[0];
    const float* Wq   = (const float*)d_in[1];
    const float* Wk   = (const float*)d_in[2];
    const float* Wv   = (const float*)d_in[3];
    const float* Wo   = (const float*)d_in[4];
    const float* ln1g = (const float*)d_in[5];
    const float* ln1b = (const float*)d_in[6];
    const float* ln2g = (const float*)d_in[7];
    const float* ln2b = (const float*)d_in[8];
    const float* W1   = (const float*)d_in[9];
    const float* b1   = (const float*)d_in[10];
    const float* W2   = (const float*)d_in[11];
    const float* b2   = (const float*)d_in[12];
    float* out = (float*)d_out;

    float *xn, *q, *k, *v, *att, *h1, *mlp, *wqkvo, *w1r, *w2r;
    cudaGetSymbolAddress((void**)&xn,    g_xn);
    cudaGetSymbolAddress((void**)&q,     g_q);
    cudaGetSymbolAddress((void**)&k,     g_k);
    cudaGetSymbolAddress((void**)&v,     g_v);
    cudaGetSymbolAddress((void**)&att,   g_att);
    cudaGetSymbolAddress((void**)&h1,    g_h1);
    cudaGetSymbolAddress((void**)&mlp,   g_mlp);
    cudaGetSymbolAddress((void**)&wqkvo, g_wqkvo);
    cudaGetSymbolAddress((void**)&w1r,   g_w1r);
    cudaGetSymbolAddress((void**)&w2r,   g_w2r);

    cudaFuncSetAttribute(attn_tc, cudaFuncAttributeMaxDynamicSharedMemorySize,
                         ATTN_SMEM);
    cudaFuncSetAttribute(gemm_qkv, cudaFuncAttributeMaxDynamicSharedMemorySize,
                         (int)GEMM_SMEM);
    cudaFuncSetAttribute(gemm_tf32<1, 1>, cudaFuncAttributeMaxDynamicSharedMemorySize,
                         (int)GEMM_SMEM);
    cudaFuncSetAttribute(gemm_tf32<2, 0>, cudaFuncAttributeMaxDynamicSharedMemorySize,
                         (int)GEMM_SMEM);
    cudaFuncSetAttribute(gemm_tf32<3, 0>, cudaFuncAttributeMaxDynamicSharedMemorySize,
                         (int)GEMM_SMEM);

    dim3 gProj(DM / 128, TOK / 128);        // 8 x 32
    dim3 gQkv(DM / 128, TOK / 128, 3);      // 8 x 32 x 3
    dim3 gMlp1(DFF / 128, TOK / 128);       // 32 x 32

    // pre-round weights to tf32 (once per launch; graph-captured)
    int n4p = DM * DM / 4;                  // 262144
    int n4f = DM * DFF / 4;                 // 1048576
    round_kernel<<<(n4p + 255) / 256, 256>>>((const float4*)Wq, (float4*)wqkvo, n4p);
    round_kernel<<<(n4p + 255) / 256, 256>>>((const float4*)Wk, (float4*)(wqkvo + DM * DM), n4p);
    round_kernel<<<(n4p + 255) / 256, 256>>>((const float4*)Wv, (float4*)(wqkvo + 2 * DM * DM), n4p);
    round_kernel<<<(n4p + 255) / 256, 256>>>((const float4*)Wo, (float4*)(wqkvo + 3 * DM * DM), n4p);
    round_kernel<<<(n4f + 255) / 256, 256>>>((const float4*)W1, (float4*)w1r, n4f);
    round_kernel<<<(n4f + 255) / 256, 256>>>((const float4*)W2, (float4*)w2r, n4f);

    // LN1
    ln_kernel<<<TOK, 256>>>(H, ln1g, ln1b, xn);
    // fused Q, K, V projections
    gemm_qkv<<<gQkv, 256, GEMM_SMEM>>>(xn, wqkvo, q, k, v, TOK, DM, DM);
    // fused causal attention (tensor cores)
    attn_tc<<<dim3(32, 16, 2), 128, ATTN_SMEM>>>(q, k, v, att);
    // O projection + residual (exact fp32 residual stream)
    gemm_tf32<3, 0><<<gProj, 256, GEMM_SMEM>>>(att, wqkvo + 3 * DM * DM, nullptr, H,
                                               h1, TOK, DM, DM);
    // LN2
    ln_kernel<<<TOK, 256>>>(h1, ln2g, ln2b, xn);
    // MLP
    gemm_tf32<1, 1><<<gMlp1, 256, GEMM_SMEM>>>(xn, w1r, b1, nullptr, mlp, TOK, DFF, DM);
    gemm_tf32<2, 0><<<gProj, 256, GEMM_SMEM>>>(mlp, w2r, b2, h1, out, TOK, DM, DFF);
}